// round 8
// baseline (speedup 1.0000x reference)
#include <cuda_runtime.h>
#include <cstdint>
#include <cstddef>

#define BATCHES 16
#define NPTS    65536
#define NSAMP   2048
#define THREADS 1024
#define PPT     64                   // consecutive points per thread

// Per-batch running min-distance buffer (4 MB). Each thread touches only its
// own 64-entry slice: thread-private, no visibility requirements.
__device__ float g_dist[BATCHES][NPTS];

// XLA/NVPTX-contracted squared distance, matching the reference's emitted
// code: d = fma(dz,dz, fma(dy,dy, dx*dx)).
static __device__ __forceinline__ float sqdist_ref(float dx, float dy, float dz) {
    return __fmaf_rn(dz, dz, __fmaf_rn(dy, dy, __fmul_rn(dx, dx)));
}

// jnp.argmax semantics: larger value wins; equal value -> smaller index wins.
static __device__ __forceinline__ void pair_max(float& v, int& p, float ov, int op) {
    if (ov > v || (ov == v && op < p)) { v = ov; p = op; }
}

__global__ void __launch_bounds__(THREADS, 1)
fps_kernel(const float* __restrict__ t_in, float* __restrict__ out)
{
    __shared__ float s_v[32];
    __shared__ int   s_i[32];
    __shared__ float s_wx, s_wy, s_wz;

    const int tid   = threadIdx.x;
    const int lane  = tid & 31;
    const int warp  = tid >> 5;
    const int batch = blockIdx.x;

    const float* __restrict__ pb = t_in + (size_t)batch * ((size_t)NPTS * 3);
    float* __restrict__ db = &g_dist[batch][0];

    // ---- init my 64 consecutive dist entries (vectorized) ----
    const int base_p = tid * PPT;
    float4* dv = (float4*)(db + base_p);
    #pragma unroll
    for (int q = 0; q < PPT / 4; q++)
        dv[q] = make_float4(1e10f, 1e10f, 1e10f, 1e10f);

    // First sample is always index 0; its coords seed the loop.
    float lx = pb[0], ly = pb[1], lz = pb[2];
    if (tid == 0) out[batch * NSAMP] = 0.0f;     // float output (harness dtype)
    __syncthreads();

    const float4* __restrict__ cv = (const float4*)(pb + (size_t)base_p * 3);

    for (int k = 1; k < NSAMP; k++) {
        // ---- update running min distance + per-thread first-max argmax ----
        float bestv = -1.0f;
        int   bestp = 0x7fffffff;
        #pragma unroll 4
        for (int q = 0; q < PPT / 4; q++) {
            // 4 points = 12 floats = 3 float4 loads (16B-aligned)
            float4 a = __ldg(cv + 3 * q + 0);
            float4 b = __ldg(cv + 3 * q + 1);
            float4 c = __ldg(cv + 3 * q + 2);
            float d0 = sqdist_ref(a.x - lx, a.y - ly, a.z - lz);
            float d1 = sqdist_ref(a.w - lx, b.x - ly, b.y - lz);
            float d2 = sqdist_ref(b.z - lx, b.w - ly, c.x - lz);
            float d3 = sqdist_ref(c.y - lx, c.z - ly, c.w - lz);
            float4 dd = dv[q];
            dd.x = fminf(dd.x, d0);
            dd.y = fminf(dd.y, d1);
            dd.z = fminf(dd.z, d2);
            dd.w = fminf(dd.w, d3);
            dv[q] = dd;
            int p0 = base_p + 4 * q;              // ascending p: strict > keeps first max
            if (dd.x > bestv) { bestv = dd.x; bestp = p0;     }
            if (dd.y > bestv) { bestv = dd.y; bestp = p0 + 1; }
            if (dd.z > bestv) { bestv = dd.z; bestp = p0 + 2; }
            if (dd.w > bestv) { bestv = dd.w; bestp = p0 + 3; }
        }

        // ---- warp argmax over (value, index) ----
        #pragma unroll
        for (int off = 16; off; off >>= 1) {
            float ov = __shfl_down_sync(0xffffffffu, bestv, off);
            int   op = __shfl_down_sync(0xffffffffu, bestp, off);
            pair_max(bestv, bestp, ov, op);
        }
        if (lane == 0) { s_v[warp] = bestv; s_i[warp] = bestp; }
        __syncthreads();

        // ---- cross-warp argmax (warp 0), publish winner coords + index ----
        if (warp == 0) {
            float v = s_v[lane];
            int   p = s_i[lane];
            #pragma unroll
            for (int off = 16; off; off >>= 1) {
                float ov = __shfl_down_sync(0xffffffffu, v, off);
                int   op = __shfl_down_sync(0xffffffffu, p, off);
                pair_max(v, p, ov, op);
            }
            if (lane == 0) {
                s_wx = pb[3 * p + 0];
                s_wy = pb[3 * p + 1];
                s_wz = pb[3 * p + 2];
                // Indices 0..65535 are exactly representable in float32.
                out[batch * NSAMP + k] = (float)p;
            }
        }
        __syncthreads();

        lx = s_wx; ly = s_wy; lz = s_wz;
    }
}

extern "C" void kernel_launch(void* const* d_in, const int* in_sizes, int n_in,
                              void* d_out, int out_size)
{
    // t_in is the largest input under any size convention (elements or bytes).
    int best = 0;
    for (int i = 1; i < n_in; i++)
        if (in_sizes[i] > in_sizes[best]) best = i;
    const float* t_in = (const float*)d_in[best];

    fps_kernel<<<BATCHES, THREADS>>>(t_in, (float*)d_out);
}

// round 9
// speedup vs baseline: 18.4911x; 18.4911x over previous
#include <cuda_runtime.h>
#include <cstdint>
#include <cstddef>

#define BATCHES 16
#define NPTS    65536
#define NSAMP   2048
#define CPB     8                    // CTAs per batch
#define NPC     (NPTS / CPB)         // 8192 points per CTA
#define THREADS 512
#define NWARPS  (THREADS / 32)       // 16
#define PPT     (NPC / THREADS)      // 16 consecutive points per thread

// smem: local copy of this CTA's coords (winner lookup only)
#define SMEM_BYTES (3 * NPC * 4)     // 96 KB

// Cross-CTA exchange state (zero-initialized; reset at kernel end so graph
// replays are deterministic). Slot: {val, idx, x, y, z, pad[3]}.
__device__ float    g_slots[2][BATCHES][CPB][8];
__device__ unsigned g_count[BATCHES];   // monotonic per-iteration arrival counter
__device__ unsigned g_done[BATCHES];    // end-of-kernel reset barrier

// Reference-matching (XLA-contracted) squared distance:
// d = fma(dz,dz, fma(dy,dy, dx*dx)).  Bit-identical to the R8 passing kernel.
static __device__ __forceinline__ float sqdist_ref(float dx, float dy, float dz) {
    return __fmaf_rn(dz, dz, __fmaf_rn(dy, dy, __fmul_rn(dx, dx)));
}

// jnp.argmax semantics: larger value wins; equal value -> smaller index wins.
static __device__ __forceinline__ void pair_max(float& v, int& p, float ov, int op) {
    if (ov > v || (ov == v && op < p)) { v = ov; p = op; }
}

__global__ void __launch_bounds__(THREADS, 1)
fps_kernel(const float* __restrict__ t_in, float* __restrict__ out)
{
    extern __shared__ float sm[];
    float* spx = sm;
    float* spy = sm + NPC;
    float* spz = sm + 2 * NPC;

    __shared__ float s_v[NWARPS];
    __shared__ int   s_i[NWARPS];
    __shared__ float s_wx, s_wy, s_wz, s_wi;

    const int tid   = threadIdx.x;
    const int lane  = tid & 31;
    const int warp  = tid >> 5;
    const int rank  = blockIdx.x & (CPB - 1);
    const int batch = blockIdx.x / CPB;

    const float* __restrict__ pb = t_in + (size_t)batch * ((size_t)NPTS * 3);

    // ---- load my 16 consecutive points into registers + smem copy ----
    const int base = rank * NPC + tid * PPT;        // within-batch global index
    float px[PPT], py[PPT], pz[PPT], dist[PPT];
    {
        const float4* p4 = (const float4*)(pb + (size_t)base * 3);  // 192B aligned
        float c[PPT * 3];
        #pragma unroll
        for (int q = 0; q < (PPT * 3) / 4; q++) {
            float4 v = __ldg(p4 + q);
            c[4 * q + 0] = v.x; c[4 * q + 1] = v.y;
            c[4 * q + 2] = v.z; c[4 * q + 3] = v.w;
        }
        #pragma unroll
        for (int j = 0; j < PPT; j++) {
            px[j] = c[3 * j]; py[j] = c[3 * j + 1]; pz[j] = c[3 * j + 2];
            dist[j] = 1e10f;
            int li = tid * PPT + j;
            spx[li] = px[j]; spy[li] = py[j]; spz[li] = pz[j];
        }
    }

    // First sample is always index 0; its coords seed the loop.
    float lx = __ldg(pb + 0), ly = __ldg(pb + 1), lz = __ldg(pb + 2);
    if (rank == 0 && tid == 0) out[batch * NSAMP] = 0.0f;
    __syncthreads();

    for (int k = 1; k < NSAMP; k++) {
        // ---- register-resident distance update + per-thread first-max ----
        float bestv = -1.0f;
        int   bestp = 0x7fffffff;
        #pragma unroll
        for (int j = 0; j < PPT; j++) {
            float d  = sqdist_ref(px[j] - lx, py[j] - ly, pz[j] - lz);
            float nd = fminf(dist[j], d);
            dist[j] = nd;
            if (nd > bestv) { bestv = nd; bestp = base + j; }  // strict >: first max
        }

        // ---- warp argmax over (value, index) ----
        #pragma unroll
        for (int off = 16; off; off >>= 1) {
            float ov = __shfl_down_sync(0xffffffffu, bestv, off);
            int   op = __shfl_down_sync(0xffffffffu, bestp, off);
            pair_max(bestv, bestp, ov, op);
        }
        if (lane == 0) { s_v[warp] = bestv; s_i[warp] = bestp; }
        __syncthreads();

        // ---- warp 0: CTA argmax -> publish slot -> barrier -> cluster winner ----
        if (warp == 0) {
            float v = (lane < NWARPS) ? s_v[lane] : -1.0f;
            int   p = (lane < NWARPS) ? s_i[lane] : 0x7fffffff;
            #pragma unroll
            for (int off = 8; off; off >>= 1) {
                float ov = __shfl_down_sync(0xffffffffu, v, off);
                int   op = __shfl_down_sync(0xffffffffu, p, off);
                pair_max(v, p, ov, op);
            }
            if (lane == 0) {
                int li = p - rank * NPC;             // CTA winner is local
                float* s = &g_slots[k & 1][batch][rank][0];
                s[0] = v;
                s[1] = (float)p;                     // idx as float (exact <= 65535)
                s[2] = spx[li];
                s[3] = spy[li];
                s[4] = spz[li];
                __threadfence();                     // release slot before arrive
                atomicAdd(&g_count[batch], 1u);
                volatile unsigned* cnt = &g_count[batch];
                unsigned target = (unsigned)(CPB * k);
                while (*cnt < target) { }            // all-resident: deadlock-free
                __threadfence();                     // acquire
            }
            __syncwarp();

            // lanes 0..7: read the 8 slots (volatile: bypass stale L1)
            float rv = -1.0f, ri = 0.0f, rx = 0.0f, ry = 0.0f, rz = 0.0f;
            if (lane < CPB) {
                volatile float* s = &g_slots[k & 1][batch][lane][0];
                rv = s[0]; ri = s[1]; rx = s[2]; ry = s[3]; rz = s[4];
            }
            // argmax over 8 slots; tie -> lowest rank (== lowest index range)
            float bv = rv; int br = lane;
            #pragma unroll
            for (int off = 4; off; off >>= 1) {
                float ov = __shfl_down_sync(0xffffffffu, bv, off);
                int   orr = __shfl_down_sync(0xffffffffu, br, off);
                pair_max(bv, br, ov, orr);
            }
            int wr = __shfl_sync(0xffffffffu, br, 0);   // winning rank
            float wi = __shfl_sync(0xffffffffu, ri, wr);
            float wx = __shfl_sync(0xffffffffu, rx, wr);
            float wy = __shfl_sync(0xffffffffu, ry, wr);
            float wz = __shfl_sync(0xffffffffu, rz, wr);
            if (lane == 0) {
                s_wx = wx; s_wy = wy; s_wz = wz; s_wi = wi;
                if (rank == 0) out[batch * NSAMP + k] = wi;
            }
        }
        __syncthreads();

        lx = s_wx; ly = s_wy; lz = s_wz;
    }

    // ---- reset exchange state for the next graph replay ----
    __syncthreads();
    if (tid == 0) {
        __threadfence();
        unsigned v = atomicAdd(&g_done[batch], 1u);
        if (v == CPB - 1) {                          // last CTA of this batch
            *(volatile unsigned*)&g_count[batch] = 0u;
            __threadfence();
            *(volatile unsigned*)&g_done[batch] = 0u;
        }
    }
}

extern "C" void kernel_launch(void* const* d_in, const int* in_sizes, int n_in,
                              void* d_out, int out_size)
{
    // t_in is the largest input under any size convention.
    int best = 0;
    for (int i = 1; i < n_in; i++)
        if (in_sizes[i] > in_sizes[best]) best = i;
    const float* t_in = (const float*)d_in[best];

    // Not a stream op; graph-capture safe.
    cudaFuncSetAttribute(fps_kernel, cudaFuncAttributeMaxDynamicSharedMemorySize,
                         SMEM_BYTES);

    fps_kernel<<<BATCHES * CPB, THREADS, SMEM_BYTES>>>(t_in, (float*)d_out);
}

// round 10
// speedup vs baseline: 21.7574x; 1.1766x over previous
#include <cuda_runtime.h>
#include <cstdint>
#include <cstddef>

#define BATCHES 16
#define NPTS    65536
#define NSAMP   2048
#define CPB     8                    // CTAs per batch = cluster size
#define NPC     (NPTS / CPB)         // 8192 points per CTA
#define THREADS 512
#define NWARPS  (THREADS / 32)       // 16
#define PPT     (NPC / THREADS)      // 16 consecutive points per thread

// dynamic smem: local copy of this CTA's coords (winner lookup only)
#define SMEM_BYTES (3 * NPC * 4)     // 96 KB

// Reference-matching (XLA-contracted) squared distance:
// d = fma(dz,dz, fma(dy,dy, dx*dx)).  Bit-identical to the passing R8/R9 kernels.
static __device__ __forceinline__ float sqdist_ref(float dx, float dy, float dz) {
    return __fmaf_rn(dz, dz, __fmaf_rn(dy, dy, __fmul_rn(dx, dx)));
}

static __device__ __forceinline__ unsigned cluster_rank_() {
    unsigned r;
    asm("mov.u32 %0, %%cluster_ctarank;" : "=r"(r));
    return r;
}
static __device__ __forceinline__ unsigned mapa_shared_(unsigned addr, unsigned target) {
    unsigned r;
    asm("mapa.shared::cluster.u32 %0, %1, %2;" : "=r"(r) : "r"(addr), "r"(target));
    return r;
}
static __device__ __forceinline__ void st_cluster_v4_(unsigned addr, unsigned a, unsigned b,
                                                      unsigned c, unsigned d) {
    asm volatile("st.shared::cluster.v4.b32 [%0], {%1,%2,%3,%4};"
                 :: "r"(addr), "r"(a), "r"(b), "r"(c), "r"(d) : "memory");
}
static __device__ __forceinline__ void st_cluster_b32_(unsigned addr, unsigned a) {
    asm volatile("st.shared::cluster.b32 [%0], %1;"
                 :: "r"(addr), "r"(a) : "memory");
}
static __device__ __forceinline__ void cluster_sync_() {
    asm volatile("barrier.cluster.arrive.aligned;" ::: "memory");
    asm volatile("barrier.cluster.wait.aligned;" ::: "memory");
}

__global__ void __launch_bounds__(THREADS, 1) __cluster_dims__(CPB, 1, 1)
fps_kernel(const float* __restrict__ t_in, float* __restrict__ out)
{
    extern __shared__ float sm[];
    float* spx = sm;
    float* spy = sm + NPC;
    float* spz = sm + 2 * NPC;

    // Double-buffered cluster slot exchange: [buf][src_rank][8] = {val, idx, x, y, z,...}
    __shared__ __align__(16) float s_slots[2][CPB][8];
    __shared__ unsigned s_v[NWARPS];
    __shared__ unsigned s_i[NWARPS];

    const int tid  = threadIdx.x;
    const int lane = tid & 31;
    const int warp = tid >> 5;
    const unsigned rank = cluster_rank_();
    const int batch = blockIdx.x / CPB;

    const float* __restrict__ pb = t_in + (size_t)batch * ((size_t)NPTS * 3);

    // ---- load my 16 consecutive points into registers + smem copy ----
    const int base = (int)rank * NPC + tid * PPT;   // within-batch global index
    float px[PPT], py[PPT], pz[PPT], dist[PPT];
    {
        const float4* p4 = (const float4*)(pb + (size_t)base * 3);  // 192B aligned
        float c[PPT * 3];
        #pragma unroll
        for (int q = 0; q < (PPT * 3) / 4; q++) {
            float4 v = __ldg(p4 + q);
            c[4 * q + 0] = v.x; c[4 * q + 1] = v.y;
            c[4 * q + 2] = v.z; c[4 * q + 3] = v.w;
        }
        #pragma unroll
        for (int j = 0; j < PPT; j++) {
            px[j] = c[3 * j]; py[j] = c[3 * j + 1]; pz[j] = c[3 * j + 2];
            dist[j] = 1e10f;
            int li = tid * PPT + j;
            spx[li] = px[j]; spy[li] = py[j]; spz[li] = pz[j];
        }
    }

    // First sample is always index 0; its coords seed the loop.
    float lx = __ldg(pb + 0), ly = __ldg(pb + 1), lz = __ldg(pb + 2);
    if (rank == 0 && tid == 0) out[batch * NSAMP] = 0.0f;
    __syncthreads();

    const unsigned slots_u32 =
        (unsigned)__cvta_generic_to_shared(&s_slots[0][0][0]);

    for (int k = 1; k < NSAMP; k++) {
        // ---- register-resident distance update + per-thread first-max ----
        float bestv = -1.0f;
        int   bestj = 0;
        #pragma unroll
        for (int j = 0; j < PPT; j++) {
            float d  = sqdist_ref(px[j] - lx, py[j] - ly, pz[j] - lz);
            float nd = fminf(dist[j], d);
            dist[j] = nd;
            if (nd > bestv) { bestv = nd; bestj = j; }  // strict >: first max (asc. j)
        }
        unsigned vb   = __float_as_uint(bestv);         // dist>=0: uint order == float order
        int      gidx = base + bestj;

        // ---- warp argmax: redux + ballot + ffs (lowest lane == lowest index) ----
        unsigned vmax = __reduce_max_sync(0xffffffffu, vb);
        unsigned eq   = __ballot_sync(0xffffffffu, vb == vmax);
        int      src  = __ffs(eq) - 1;
        int      widx = __shfl_sync(0xffffffffu, gidx, src);
        if (lane == 0) { s_v[warp] = vmax; s_i[warp] = (unsigned)widx; }
        __syncthreads();

        // ---- warp 0: CTA argmax, push winner slot into all 8 CTAs' smem ----
        if (warp == 0) {
            unsigned v  = (lane < NWARPS) ? s_v[lane] : 0u;   // warps asc == index asc
            unsigned vm = __reduce_max_sync(0xffffffffu, v);
            unsigned e2 = __ballot_sync(0xffffffffu, v == vm);
            int      s2 = __ffs(e2) - 1;
            unsigned cidx = s_i[s2];                          // CTA winner index

            if (lane < CPB) {
                int li = (int)cidx - (int)rank * NPC;         // winner is CTA-local
                unsigned xb = __float_as_uint(spx[li]);
                unsigned yb = __float_as_uint(spy[li]);
                unsigned zb = __float_as_uint(spz[li]);
                unsigned la = slots_u32 + (((unsigned)(k & 1) * CPB + rank) * 8u) * 4u;
                unsigned ra = mapa_shared_(la, (unsigned)lane);
                st_cluster_v4_(ra, vm, __float_as_uint(__uint2float_rn(cidx)), xb, yb);
                st_cluster_b32_(ra + 16u, zb);
            }
        }
        // barrier.cluster: arrive releases the DSMEM stores, wait acquires them.
        cluster_sync_();

        // ---- every thread scans the 8 local slots for the batch winner ----
        const float* ss = &s_slots[k & 1][0][0];
        unsigned bb = 0u;
        int      bs = 0;
        #pragma unroll
        for (int s = 0; s < CPB; s++) {
            unsigned v = __float_as_uint(ss[s * 8]);
            if (v > bb) { bb = v; bs = s; }                   // strict >: lowest rank wins tie
        }
        const float* w = ss + bs * 8;
        lx = w[2]; ly = w[3]; lz = w[4];

        if (rank == 0 && tid == 0) out[batch * NSAMP + k] = w[1];
    }
}

extern "C" void kernel_launch(void* const* d_in, const int* in_sizes, int n_in,
                              void* d_out, int out_size)
{
    // t_in is the largest input under any size convention.
    int best = 0;
    for (int i = 1; i < n_in; i++)
        if (in_sizes[i] > in_sizes[best]) best = i;
    const float* t_in = (const float*)d_in[best];

    // Not a stream op; graph-capture safe.
    cudaFuncSetAttribute(fps_kernel, cudaFuncAttributeMaxDynamicSharedMemorySize,
                         SMEM_BYTES);

    fps_kernel<<<BATCHES * CPB, THREADS, SMEM_BYTES>>>(t_in, (float*)d_out);
}